// round 10
// baseline (speedup 1.0000x reference)
#include <cuda_runtime.h>
#include <cstdint>

#define BNS 0.9999950000375f  // 1/sqrt(1+1e-5)
constexpr int B = 16;
constexpr int N = 2048;

// ----------------- device scratch (no allocations) -----------------
__device__ float g_dist[(size_t)B * N * N];      // 268 MB
__device__ float g_xx[B * N];
__device__ int   g_idx[B * N * 20];
__device__ float g_fta[(size_t)B * N * 256];     // point-major feats (ping)
__device__ float g_ftb[(size_t)B * N * 128];     // point-major feats (pong)
__device__ float g_xc[(size_t)B * 512 * N];      // channel-major concat feats
__device__ float g_base[(size_t)B * 256 * N];
__device__ float g_y[(size_t)B * 1024 * N];
__device__ float g_wdt[128 * 256];
__device__ float g_wct[128 * 256];
__device__ float g_w5t[512 * 1024];
__device__ float g_pool[B * 2048];
__device__ float g_h1[B * 512];
__device__ float g_h2[B * 256];

// ----------------- tiny helpers -----------------
__global__ void k_xpose3(const float* __restrict__ x, float* __restrict__ ft) {
    int b = blockIdx.y, n = blockIdx.x * 256 + threadIdx.x;
    const float* xb = x + (size_t)b * 3 * N;
    float* tp = ft + ((size_t)b * N + n) * 3;
    tp[0] = xb[n]; tp[1] = xb[N + n]; tp[2] = xb[2 * N + n];
}

// W (O x rstride) submatrix cols [0,C) -> Wt (C x O)
__global__ void k_trs(const float* __restrict__ W, int rstride, int O, int C,
                      float* __restrict__ Wt) {
    int t = blockIdx.x * 256 + threadIdx.x;
    if (t >= O * C) return;
    int o = t / C, c = t - o * C;
    Wt[c * O + o] = W[(size_t)o * rstride + c];
}

__global__ void k_xx(const float* __restrict__ F, size_t bstride, int C,
                     float* __restrict__ xx) {
    int b = blockIdx.y, i = blockIdx.x * 256 + threadIdx.x;
    const float* Fb = F + (size_t)b * bstride;
    float s = 0.f;
    for (int c = 0; c < C; c++) { float v = Fb[(size_t)c * N + i]; s = fmaf(v, v, s); }
    xx[b * N + i] = s;
}

// ----------------- dist GEMM: dist = 2*F^T F - xx_i - xx_j -----------------
__global__ __launch_bounds__(256) void k_dist(const float* __restrict__ F, size_t bstride,
                       int C, const float* __restrict__ xx, float* __restrict__ dist) {
    __shared__ float sA[16][64];
    __shared__ float sB[16][64];
    int b = blockIdx.z, i0 = blockIdx.y * 64, j0 = blockIdx.x * 64;
    const float* Fb = F + (size_t)b * bstride;
    int tid = threadIdx.x, tx = tid & 15, ty = tid >> 4;
    float acc[4][4] = {};
    for (int c0 = 0; c0 < C; c0 += 16) {
        for (int t = tid; t < 1024; t += 256) {
            int kk = t >> 6, e = t & 63, c = c0 + kk;
            sA[kk][e] = (c < C) ? Fb[(size_t)c * N + i0 + e] : 0.f;
            sB[kk][e] = (c < C) ? Fb[(size_t)c * N + j0 + e] : 0.f;
        }
        __syncthreads();
#pragma unroll
        for (int kk = 0; kk < 16; kk++) {
            float4 a4 = *(const float4*)&sA[kk][ty * 4];
            float4 b4 = *(const float4*)&sB[kk][tx * 4];
            float a[4] = {a4.x, a4.y, a4.z, a4.w};
            float bv[4] = {b4.x, b4.y, b4.z, b4.w};
#pragma unroll
            for (int i = 0; i < 4; i++)
#pragma unroll
                for (int j = 0; j < 4; j++) acc[i][j] = fmaf(a[i], bv[j], acc[i][j]);
        }
        __syncthreads();
    }
    const float* xb = xx + b * N;
#pragma unroll
    for (int i = 0; i < 4; i++) {
        float xi = xb[i0 + ty * 4 + i];
#pragma unroll
        for (int j = 0; j < 4; j++)
            dist[((size_t)b * N + i0 + ty * 4 + i) * N + j0 + tx * 4 + j] =
                2.f * acc[i][j] - xi - xb[j0 + tx * 4 + j];
    }
}

// ----------------- generic GEMM: out[b][o][n] = sum_c Wt[c][o]*F[b][c][n] -----------------
template <int EPI>
__global__ __launch_bounds__(256) void k_gemm(const float* __restrict__ Wt, int O,
                       const float* __restrict__ F, size_t bstride, int C,
                       float* __restrict__ outp,
                       const float* __restrict__ g, const float* __restrict__ bb) {
    __shared__ float sA[16][64];
    __shared__ float sB[16][64];
    int b = blockIdx.z, o0 = blockIdx.y * 64, n0 = blockIdx.x * 64;
    const float* Fb = F + (size_t)b * bstride;
    int tid = threadIdx.x, tx = tid & 15, ty = tid >> 4;
    float acc[4][4] = {};
    for (int c0 = 0; c0 < C; c0 += 16) {
        for (int t = tid; t < 1024; t += 256) {
            int kk = t >> 6, e = t & 63, c = c0 + kk;
            sA[kk][e] = (c < C) ? Wt[(size_t)c * O + o0 + e] : 0.f;
            sB[kk][e] = (c < C) ? Fb[(size_t)c * N + n0 + e] : 0.f;
        }
        __syncthreads();
#pragma unroll
        for (int kk = 0; kk < 16; kk++) {
            float4 a4 = *(const float4*)&sA[kk][ty * 4];
            float4 b4 = *(const float4*)&sB[kk][tx * 4];
            float a[4] = {a4.x, a4.y, a4.z, a4.w};
            float bv[4] = {b4.x, b4.y, b4.z, b4.w};
#pragma unroll
            for (int i = 0; i < 4; i++)
#pragma unroll
                for (int j = 0; j < 4; j++) acc[i][j] = fmaf(a[i], bv[j], acc[i][j]);
        }
        __syncthreads();
    }
#pragma unroll
    for (int i = 0; i < 4; i++) {
        int o = o0 + ty * 4 + i;
        float s = 0.f, bi = 0.f;
        if (EPI == 1) { s = g[o] * BNS; bi = bb[o]; }
#pragma unroll
        for (int j = 0; j < 4; j++) {
            float v = acc[i][j];
            if (EPI == 1) { v = v * s + bi; v = v < 0.f ? 0.2f * v : v; }
            outp[((size_t)b * O + o) * N + n0 + tx * 4 + j] = v;
        }
    }
}

// ----------------- warp-per-row top-20 -----------------
__global__ void k_topk(const float* __restrict__ dist, int* __restrict__ idxo) {
    int row = blockIdx.x * 8 + (threadIdx.x >> 5);
    int lane = threadIdx.x & 31;
    const float* dr = dist + (size_t)row * N;
    float tv[20]; int tj[20];
#pragma unroll
    for (int i = 0; i < 20; i++) { tv[i] = -3e38f; tj[i] = 0; }
    for (int s = 0; s < N / 32; s++) {
        int j = s * 32 + lane;
        float d = dr[j];
        if (d > tv[19]) {
            float cv = d; int cj = j;
#pragma unroll
            for (int t = 0; t < 20; t++) {
                if (cv > tv[t]) {
                    float fv = tv[t]; int fj = tj[t];
                    tv[t] = cv; tj[t] = cj; cv = fv; cj = fj;
                }
            }
        }
    }
    int* orow = idxo + (size_t)row * 20;
    for (int r = 0; r < 20; r++) {
        float bv = tv[0]; int bl = lane;
#pragma unroll
        for (int off = 16; off; off >>= 1) {
            float ov = __shfl_xor_sync(0xffffffffu, bv, off);
            int   ol = __shfl_xor_sync(0xffffffffu, bl, off);
            if (ov > bv) { bv = ov; bl = ol; }
        }
        int jw = __shfl_sync(0xffffffffu, tj[0], bl);
        if (lane == 0) orow[r] = jw;
        if (lane == bl) {
#pragma unroll
            for (int t = 0; t < 19; t++) { tv[t] = tv[t + 1]; tj[t] = tj[t + 1]; }
            tv[19] = -3e38f;
        }
    }
}

// ----------------- fused edge conv: max_k Wd.(nbr-ctr) + base, BN+lrelu -----------------
// grid (N/4, O/64, B), 256 thr. M=80 rows (k-major: row = k*4 + p).
template <int C, int O>
__global__ __launch_bounds__(256) void k_edge(const float* __restrict__ Wdt,
                       const float* __restrict__ ft, const int* __restrict__ idx,
                       const float* __restrict__ base, float* __restrict__ xc,
                       float* __restrict__ ftout,
                       const float* __restrict__ g, const float* __restrict__ bb,
                       int choff) {
    extern __shared__ float sm[];
    float* sW = sm;                      // [C][64]
    float* sD = sm + C * 64;             // [80][C]
    int*   sI = (int*)(sD + 80 * C);     // [80]
    float* red = (float*)(sI + 80);      // [16][64]
    int b = blockIdx.z, o0 = blockIdx.y * 64, nb = blockIdx.x * 4;
    int tid = threadIdx.x;
    for (int t = tid; t < C * 64; t += 256)
        sW[t] = Wdt[(t >> 6) * O + o0 + (t & 63)];
    if (tid < 80)
        sI[tid] = idx[((size_t)(b * N + nb + (tid & 3))) * 20 + (tid >> 2)];
    __syncthreads();
    const float* fb = ft + (size_t)b * N * C;
    for (int t = tid; t < 80 * C; t += 256) {
        int row = t / C, c = t - row * C;
        int j = sI[row];
        sD[t] = fb[(size_t)j * C + c] - fb[(size_t)(nb + (row & 3)) * C + c];
    }
    __syncthreads();
    int tx = tid & 15, ty = tid >> 4;
    int p = ty & 3, q = ty >> 2;
    float acc[5][4] = {};
#pragma unroll 4
    for (int c = 0; c < C; c++) {
        float4 w4 = *(const float4*)&sW[c * 64 + tx * 4];
#pragma unroll
        for (int r = 0; r < 5; r++) {
            float d = sD[((q + 4 * r) * 4 + p) * C + c];
            acc[r][0] = fmaf(d, w4.x, acc[r][0]);
            acc[r][1] = fmaf(d, w4.y, acc[r][1]);
            acc[r][2] = fmaf(d, w4.z, acc[r][2]);
            acc[r][3] = fmaf(d, w4.w, acc[r][3]);
        }
    }
#pragma unroll
    for (int j = 0; j < 4; j++) {
        float m = acc[0][j];
#pragma unroll
        for (int r = 1; r < 5; r++) m = fmaxf(m, acc[r][j]);
        red[ty * 64 + tx * 4 + j] = m;
    }
    __syncthreads();
    if (ty < 4) {
        int n = nb + ty;
#pragma unroll
        for (int j = 0; j < 4; j++) {
            int oo = tx * 4 + j, o = o0 + oo;
            float v = red[ty * 64 + oo];
            v = fmaxf(v, red[(ty + 4) * 64 + oo]);
            v = fmaxf(v, red[(ty + 8) * 64 + oo]);
            v = fmaxf(v, red[(ty + 12) * 64 + oo]);
            v += base[((size_t)b * O + o) * N + n];
            v = v * (g[o] * BNS) + bb[o];
            v = v < 0.f ? 0.2f * v : v;
            xc[((size_t)b * 512 + choff + o) * N + n] = v;
            ftout[((size_t)(b * N + n)) * O + o] = v;
        }
    }
}

// ----------------- pooling + FC head -----------------
__global__ void k_pool(const float* __restrict__ y, float* __restrict__ p) {
    __shared__ float smx[256], ssm[256];
    int b = blockIdx.y, o = blockIdx.x, tid = threadIdx.x;
    const float* row = y + ((size_t)b * 1024 + o) * N;
    float mx = -3e38f, sm = 0.f;
    for (int n = tid; n < N; n += 256) { float v = row[n]; mx = fmaxf(mx, v); sm += v; }
    smx[tid] = mx; ssm[tid] = sm; __syncthreads();
    for (int s = 128; s; s >>= 1) {
        if (tid < s) { smx[tid] = fmaxf(smx[tid], smx[tid + s]); ssm[tid] += ssm[tid + s]; }
        __syncthreads();
    }
    if (tid == 0) { p[b * 2048 + o] = smx[0]; p[b * 2048 + 1024 + o] = ssm[0] * (1.f / 2048.f); }
}

template <int MODE>  // 0: +bias, 1: (+bias)+BN+lrelu
__global__ void k_fc(const float* __restrict__ in, int Cin, const float* __restrict__ W,
                     const float* __restrict__ bias, const float* __restrict__ g,
                     const float* __restrict__ bb, int O, float* __restrict__ outp) {
    int gw = (blockIdx.x * blockDim.x + threadIdx.x) >> 5;
    int lane = threadIdx.x & 31;
    if (gw >= 16 * O) return;
    int b = gw / O, o = gw - b * O;
    const float* ib = in + (size_t)b * Cin;
    const float* wr = W + (size_t)o * Cin;
    float s = 0.f;
    for (int c = lane; c < Cin; c += 32) s = fmaf(ib[c], wr[c], s);
#pragma unroll
    for (int off = 16; off; off >>= 1) s += __shfl_xor_sync(0xffffffffu, s, off);
    if (lane == 0) {
        float v = s + (bias ? bias[o] : 0.f);
        if (MODE == 1) { v = v * (g[o] * BNS) + bb[o]; v = v < 0.f ? 0.2f * v : v; }
        outp[b * O + o] = v;
    }
}

static size_t edge_smem(int C) { return (size_t)(C * 64 + 80 * C) * 4 + 320 + 4096; }

extern "C" void kernel_launch(void* const* d_in, const int* in_sizes, int n_in,
                              void* d_out, int out_size) {
    (void)in_sizes; (void)n_in; (void)out_size;
    const float* x  = (const float*)d_in[0];
    const float* W1 = (const float*)d_in[1];
    const float* W2 = (const float*)d_in[2];
    const float* W3 = (const float*)d_in[3];
    const float* W4 = (const float*)d_in[4];
    const float* W5 = (const float*)d_in[5];
    const float *gs[7], *bs[7];
    for (int i = 0; i < 7; i++) { gs[i] = (const float*)d_in[6 + 2 * i]; bs[i] = (const float*)d_in[7 + 2 * i]; }
    const float* L1w = (const float*)d_in[20];
    const float* L2w = (const float*)d_in[21];
    const float* L2b = (const float*)d_in[22];
    const float* L3w = (const float*)d_in[23];
    const float* L3b = (const float*)d_in[24];
    float* out = (float*)d_out;

    float *dist, *xxp, *fta, *ftb, *xc, *basep, *yp, *wdt, *wct, *w5t, *poolp, *h1, *h2;
    int* idxp;
    cudaGetSymbolAddress((void**)&dist, g_dist);
    cudaGetSymbolAddress((void**)&xxp, g_xx);
    cudaGetSymbolAddress((void**)&idxp, g_idx);
    cudaGetSymbolAddress((void**)&fta, g_fta);
    cudaGetSymbolAddress((void**)&ftb, g_ftb);
    cudaGetSymbolAddress((void**)&xc, g_xc);
    cudaGetSymbolAddress((void**)&basep, g_base);
    cudaGetSymbolAddress((void**)&yp, g_y);
    cudaGetSymbolAddress((void**)&wdt, g_wdt);
    cudaGetSymbolAddress((void**)&wct, g_wct);
    cudaGetSymbolAddress((void**)&w5t, g_w5t);
    cudaGetSymbolAddress((void**)&poolp, g_pool);
    cudaGetSymbolAddress((void**)&h1, g_h1);
    cudaGetSymbolAddress((void**)&h2, g_h2);

    cudaFuncSetAttribute(k_edge<128, 256>, cudaFuncAttributeMaxDynamicSharedMemorySize,
                         (int)edge_smem(128));

    dim3 thr(256);
    size_t bs512 = (size_t)512 * N;

    k_xpose3<<<dim3(N / 256, B), thr>>>(x, fta);

    // ---- stage 1: C=3, O=64 ----
    k_trs<<<1, thr>>>(W1, 6, 64, 3, wdt);
    k_trs<<<1, thr>>>(W1 + 3, 6, 64, 3, wct);
    k_xx<<<dim3(N / 256, B), thr>>>(x, (size_t)3 * N, 3, xxp);
    k_dist<<<dim3(32, 32, B), thr>>>(x, (size_t)3 * N, 3, xxp, dist);
    k_topk<<<B * N / 8, thr>>>(dist, idxp);
    k_gemm<0><<<dim3(32, 1, B), thr>>>(wct, 64, x, (size_t)3 * N, 3, basep, nullptr, nullptr);
    k_edge<3, 64><<<dim3(N / 4, 1, B), thr, edge_smem(3)>>>(wdt, fta, idxp, basep, xc, ftb, gs[0], bs[0], 0);

    // ---- stage 2: C=64, O=64, input = x1 (xc choff 0, ftb) ----
    k_trs<<<16, thr>>>(W2, 128, 64, 64, wdt);
    k_trs<<<16, thr>>>(W2 + 64, 128, 64, 64, wct);
    k_xx<<<dim3(N / 256, B), thr>>>(xc, bs512, 64, xxp);
    k_dist<<<dim3(32, 32, B), thr>>>(xc, bs512, 64, xxp, dist);
    k_topk<<<B * N / 8, thr>>>(dist, idxp);
    k_gemm<0><<<dim3(32, 1, B), thr>>>(wct, 64, xc, bs512, 64, basep, nullptr, nullptr);
    k_edge<64, 64><<<dim3(N / 4, 1, B), thr, edge_smem(64)>>>(wdt, ftb, idxp, basep, xc, fta, gs[1], bs[1], 64);

    // ---- stage 3: C=64, O=128, input = x2 (xc choff 64, fta) ----
    const float* F3 = xc + (size_t)64 * N;
    k_trs<<<32, thr>>>(W3, 128, 128, 64, wdt);
    k_trs<<<32, thr>>>(W3 + 64, 128, 128, 64, wct);
    k_xx<<<dim3(N / 256, B), thr>>>(F3, bs512, 64, xxp);
    k_dist<<<dim3(32, 32, B), thr>>>(F3, bs512, 64, xxp, dist);
    k_topk<<<B * N / 8, thr>>>(dist, idxp);
    k_gemm<0><<<dim3(32, 2, B), thr>>>(wct, 128, F3, bs512, 64, basep, nullptr, nullptr);
    k_edge<64, 128><<<dim3(N / 4, 2, B), thr, edge_smem(64)>>>(wdt, fta, idxp, basep, xc, ftb, gs[2], bs[2], 128);

    // ---- stage 4: C=128, O=256, input = x3 (xc choff 128, ftb) ----
    const float* F4 = xc + (size_t)128 * N;
    k_trs<<<128, thr>>>(W4, 256, 256, 128, wdt);
    k_trs<<<128, thr>>>(W4 + 128, 256, 256, 128, wct);
    k_xx<<<dim3(N / 256, B), thr>>>(F4, bs512, 128, xxp);
    k_dist<<<dim3(32, 32, B), thr>>>(F4, bs512, 128, xxp, dist);
    k_topk<<<B * N / 8, thr>>>(dist, idxp);
    k_gemm<0><<<dim3(32, 4, B), thr>>>(wct, 256, F4, bs512, 128, basep, nullptr, nullptr);
    k_edge<128, 256><<<dim3(N / 4, 4, B), thr, edge_smem(128)>>>(wdt, ftb, idxp, basep, xc, fta, gs[3], bs[3], 256);

    // ---- conv5 + pooling + head ----
    k_trs<<<2048, thr>>>(W5, 512, 1024, 512, w5t);
    k_gemm<1><<<dim3(32, 16, B), thr>>>(w5t, 1024, xc, bs512, 512, yp, gs[4], bs[4]);
    k_pool<<<dim3(1024, B), thr>>>(yp, poolp);
    k_fc<1><<<(16 * 512 * 32) / 256, thr>>>(poolp, 2048, L1w, nullptr, gs[5], bs[5], 512, h1);
    k_fc<1><<<(16 * 256 * 32) / 256, thr>>>(h1, 512, L2w, L2b, gs[6], bs[6], 256, h2);
    k_fc<0><<<(16 * 40 * 32 + 255) / 256, thr>>>(h2, 256, L3w, L3b, nullptr, nullptr, 40, out);
}

// round 11
// speedup vs baseline: 1.4461x; 1.4461x over previous
#include <cuda_runtime.h>
#include <cstdint>

#define BNS 0.9999950000375f  // 1/sqrt(1+1e-5)
constexpr int B = 16;
constexpr int N = 2048;

// ----------------- device scratch (no allocations) -----------------
__device__ float g_dist[(size_t)B * N * N];        // 268 MB
__device__ float g_xx[B * N];
__device__ int   g_idx[B * N * 20];
__device__ float g_xc[(size_t)B * 512 * N];        // channel-major concat feats
__device__ float g_pq[(size_t)B * N * 512];        // point-major P|Q per stage
__device__ float g_y[(size_t)B * 1024 * N];
__device__ float g_wcat[128 * 512];                // Wt_cat: C x 2O
__device__ float g_w5t[512 * 1024];
__device__ float g_pool[B * 2048];
__device__ float g_h1[B * 512];
__device__ float g_h2[B * 256];

// ----------------- helpers -----------------
// build Wt_cat (C x 2O): cols [0,O) = Wd = W[:,0:C]; cols [O,2O) = Wc - Wd
__global__ void k_wprep(const float* __restrict__ W, int O, int C, float* __restrict__ Wt) {
    int t = blockIdx.x * 256 + threadIdx.x;
    if (t >= O * C) return;
    int o = t / C, c = t - o * C;
    float wd = W[(size_t)o * 2 * C + c];
    float wc = W[(size_t)o * 2 * C + C + c];
    Wt[(size_t)c * 2 * O + o] = wd;
    Wt[(size_t)c * 2 * O + O + o] = wc - wd;
}

// W (O x rstride) cols [0,C) -> Wt (C x O)
__global__ void k_trs(const float* __restrict__ W, int rstride, int O, int C,
                      float* __restrict__ Wt) {
    int t = blockIdx.x * 256 + threadIdx.x;
    if (t >= O * C) return;
    int o = t / C, c = t - o * C;
    Wt[(size_t)c * O + o] = W[(size_t)o * rstride + c];
}

__global__ void k_xx(const float* __restrict__ F, size_t bstride, int C,
                     float* __restrict__ xx) {
    int b = blockIdx.y, i = blockIdx.x * 256 + threadIdx.x;
    const float* Fb = F + (size_t)b * bstride;
    float s = 0.f;
    for (int c = 0; c < C; c++) { float v = Fb[(size_t)c * N + i]; s = fmaf(v, v, s); }
    xx[b * N + i] = s;
}

// ----------------- 128x128 tiled GEMM, 8x8 per thread -----------------
// acc[i][j] = sum_c A[c][o0+ty*8+i] * Bm[c][n0+tx*8+j]
// EPI 0: dist   out[(b*N+row)*N+col] = 2*acc - xx[row] - xx[col]      (e1 = xx)
// EPI 1: PM     out[(b*N+col)*M+row] = acc                            (point-major)
// EPI 2: BN     out[(b*M+row)*N+col] = lrelu(acc*g*BNS + bb)          (e1=g, e2=bb)
template <int EPI>
__global__ __launch_bounds__(256, 2) void k_g128(
    const float* __restrict__ A, size_t a_bs, int lda,
    const float* __restrict__ Bm, size_t b_bs,
    int C, int M, float* __restrict__ out,
    const float* __restrict__ e1, const float* __restrict__ e2) {
    __shared__ float sA[8][128];
    __shared__ float sB[8][128];
    int b = blockIdx.z, o0 = blockIdx.y * 128, n0 = blockIdx.x * 128;
    const float* Ab = A + (size_t)b * a_bs;
    const float* Bb = Bm + (size_t)b * b_bs;
    int tid = threadIdx.x, tx = tid & 15, ty = tid >> 4;
    int lr = tid >> 5, lc = (tid & 31) * 4;
    float acc[8][8] = {};
    for (int c0 = 0; c0 < C; c0 += 8) {
        int c = c0 + lr;
        float4 va = make_float4(0.f, 0.f, 0.f, 0.f), vb = va;
        if (c < C) {
            va = *(const float4*)&Ab[(size_t)c * lda + o0 + lc];
            vb = *(const float4*)&Bb[(size_t)c * N + n0 + lc];
        }
        *(float4*)&sA[lr][lc] = va;
        *(float4*)&sB[lr][lc] = vb;
        __syncthreads();
#pragma unroll
        for (int kk = 0; kk < 8; kk++) {
            float a[8], bv[8];
            *(float4*)&a[0]  = *(const float4*)&sA[kk][ty * 8];
            *(float4*)&a[4]  = *(const float4*)&sA[kk][ty * 8 + 4];
            *(float4*)&bv[0] = *(const float4*)&sB[kk][tx * 8];
            *(float4*)&bv[4] = *(const float4*)&sB[kk][tx * 8 + 4];
#pragma unroll
            for (int i = 0; i < 8; i++)
#pragma unroll
                for (int j = 0; j < 8; j++) acc[i][j] = fmaf(a[i], bv[j], acc[i][j]);
        }
        __syncthreads();
    }
    if (EPI == 0) {
        const float* xb = e1 + b * N;
#pragma unroll
        for (int i = 0; i < 8; i++) {
            int row = o0 + ty * 8 + i;
            float xi = xb[row];
            float* orow = out + ((size_t)b * N + row) * N + n0 + tx * 8;
#pragma unroll
            for (int j = 0; j < 8; j++)
                orow[j] = 2.f * acc[i][j] - xi - xb[n0 + tx * 8 + j];
        }
    } else if (EPI == 1) {
#pragma unroll
        for (int j = 0; j < 8; j++) {
            int col = n0 + tx * 8 + j;
            float* oc = out + ((size_t)b * N + col) * M + o0 + ty * 8;
            float4 v0 = make_float4(acc[0][j], acc[1][j], acc[2][j], acc[3][j]);
            float4 v1 = make_float4(acc[4][j], acc[5][j], acc[6][j], acc[7][j]);
            *(float4*)&oc[0] = v0;
            *(float4*)&oc[4] = v1;
        }
    } else {
#pragma unroll
        for (int i = 0; i < 8; i++) {
            int row = o0 + ty * 8 + i;
            float s = e1[row] * BNS, bi = e2[row];
            float* orow = out + ((size_t)b * M + row) * N + n0 + tx * 8;
#pragma unroll
            for (int j = 0; j < 8; j++) {
                float v = acc[i][j] * s + bi;
                orow[j] = v < 0.f ? 0.2f * v : v;
            }
        }
    }
}

// ----------------- warp-per-row top-20 -----------------
__global__ void k_topk(const float* __restrict__ dist, int* __restrict__ idxo) {
    int row = blockIdx.x * 8 + (threadIdx.x >> 5);
    int lane = threadIdx.x & 31;
    const float* dr = dist + (size_t)row * N;
    float tv[20]; int tj[20];
#pragma unroll
    for (int i = 0; i < 20; i++) { tv[i] = -3e38f; tj[i] = 0; }
    for (int s = 0; s < N / 32; s++) {
        int j = s * 32 + lane;
        float d = dr[j];
        if (d > tv[19]) {
            float cv = d; int cj = j;
#pragma unroll
            for (int t = 0; t < 20; t++) {
                if (cv > tv[t]) {
                    float fv = tv[t]; int fj = tj[t];
                    tv[t] = cv; tj[t] = cj; cv = fv; cj = fj;
                }
            }
        }
    }
    int* orow = idxo + (size_t)row * 20;
    for (int r = 0; r < 20; r++) {
        float bv = tv[0]; int bl = lane;
#pragma unroll
        for (int off = 16; off; off >>= 1) {
            float ov = __shfl_xor_sync(0xffffffffu, bv, off);
            int   ol = __shfl_xor_sync(0xffffffffu, bl, off);
            if (ov > bv) { bv = ov; bl = ol; }
        }
        int jw = __shfl_sync(0xffffffffu, tj[0], bl);
        if (lane == 0) orow[r] = jw;
        if (lane == bl) {
#pragma unroll
            for (int t = 0; t < 19; t++) { tv[t] = tv[t + 1]; tj[t] = tj[t + 1]; }
            tv[19] = -3e38f;
        }
    }
}

// ----------------- gather-max + BN + lrelu -----------------
// PQ point-major (B,N,2O). out[o][n] = lrelu(bn(max_k PQ[idx[n][k]][o] + PQ[n][O+o]))
template <int O>
__global__ void k_gmax(const float* __restrict__ PQ, const int* __restrict__ idx,
                       const float* __restrict__ g, const float* __restrict__ bb,
                       float* __restrict__ xc, int choff) {
    constexpr int PTS = 256 / O;
    int b = blockIdx.y;
    int n = blockIdx.x * PTS + (threadIdx.x >> (O == 64 ? 6 : (O == 128 ? 7 : 8)));
    int o = threadIdx.x & (O - 1);
    const float* Pb = PQ + (size_t)b * N * (2 * O);
    const int* ir = idx + ((size_t)b * N + n) * 20;
    float m = -3e38f;
#pragma unroll
    for (int k = 0; k < 20; k++) {
        int j = __ldg(&ir[k]);
        m = fmaxf(m, __ldg(&Pb[(size_t)j * (2 * O) + o]));
    }
    float v = m + Pb[(size_t)n * (2 * O) + O + o];
    v = v * (g[o] * BNS) + bb[o];
    v = v < 0.f ? 0.2f * v : v;
    xc[((size_t)b * 512 + choff + o) * N + n] = v;
}

// ----------------- pooling + FC head -----------------
__global__ void k_pool(const float* __restrict__ y, float* __restrict__ p) {
    __shared__ float smx[256], ssm[256];
    int b = blockIdx.y, o = blockIdx.x, tid = threadIdx.x;
    const float* row = y + ((size_t)b * 1024 + o) * N;
    float mx = -3e38f, sm = 0.f;
    for (int n = tid; n < N; n += 256) { float v = row[n]; mx = fmaxf(mx, v); sm += v; }
    smx[tid] = mx; ssm[tid] = sm; __syncthreads();
    for (int s = 128; s; s >>= 1) {
        if (tid < s) { smx[tid] = fmaxf(smx[tid], smx[tid + s]); ssm[tid] += ssm[tid + s]; }
        __syncthreads();
    }
    if (tid == 0) { p[b * 2048 + o] = smx[0]; p[b * 2048 + 1024 + o] = ssm[0] * (1.f / 2048.f); }
}

template <int MODE>  // 0: +bias, 1: (+bias)+BN+lrelu
__global__ void k_fc(const float* __restrict__ in, int Cin, const float* __restrict__ W,
                     const float* __restrict__ bias, const float* __restrict__ g,
                     const float* __restrict__ bb, int O, float* __restrict__ outp) {
    int gw = (blockIdx.x * blockDim.x + threadIdx.x) >> 5;
    int lane = threadIdx.x & 31;
    if (gw >= 16 * O) return;
    int b = gw / O, o = gw - b * O;
    const float* ib = in + (size_t)b * Cin;
    const float* wr = W + (size_t)o * Cin;
    float s = 0.f;
    for (int c = lane; c < Cin; c += 32) s = fmaf(ib[c], wr[c], s);
#pragma unroll
    for (int off = 16; off; off >>= 1) s += __shfl_xor_sync(0xffffffffu, s, off);
    if (lane == 0) {
        float v = s + (bias ? bias[o] : 0.f);
        if (MODE == 1) { v = v * (g[o] * BNS) + bb[o]; v = v < 0.f ? 0.2f * v : v; }
        outp[b * O + o] = v;
    }
}

extern "C" void kernel_launch(void* const* d_in, const int* in_sizes, int n_in,
                              void* d_out, int out_size) {
    (void)in_sizes; (void)n_in; (void)out_size;
    const float* x  = (const float*)d_in[0];
    const float* W1 = (const float*)d_in[1];
    const float* W2 = (const float*)d_in[2];
    const float* W3 = (const float*)d_in[3];
    const float* W4 = (const float*)d_in[4];
    const float* W5 = (const float*)d_in[5];
    const float *gs[7], *bs[7];
    for (int i = 0; i < 7; i++) { gs[i] = (const float*)d_in[6 + 2 * i]; bs[i] = (const float*)d_in[7 + 2 * i]; }
    const float* L1w = (const float*)d_in[20];
    const float* L2w = (const float*)d_in[21];
    const float* L2b = (const float*)d_in[22];
    const float* L3w = (const float*)d_in[23];
    const float* L3b = (const float*)d_in[24];
    float* out = (float*)d_out;

    float *dist, *xxp, *xc, *pq, *yp, *wcat, *w5t, *poolp, *h1, *h2;
    int* idxp;
    cudaGetSymbolAddress((void**)&dist, g_dist);
    cudaGetSymbolAddress((void**)&xxp, g_xx);
    cudaGetSymbolAddress((void**)&idxp, g_idx);
    cudaGetSymbolAddress((void**)&xc, g_xc);
    cudaGetSymbolAddress((void**)&pq, g_pq);
    cudaGetSymbolAddress((void**)&yp, g_y);
    cudaGetSymbolAddress((void**)&wcat, g_wcat);
    cudaGetSymbolAddress((void**)&w5t, g_w5t);
    cudaGetSymbolAddress((void**)&poolp, g_pool);
    cudaGetSymbolAddress((void**)&h1, g_h1);
    cudaGetSymbolAddress((void**)&h2, g_h2);

    dim3 thr(256);
    size_t bs512 = (size_t)512 * N;

    // ---- stage 1: F=x, C=3, O=64, choff=0 ----
    k_wprep<<<1, thr>>>(W1, 64, 3, wcat);
    k_xx<<<dim3(N / 256, B), thr>>>(x, (size_t)3 * N, 3, xxp);
    k_g128<0><<<dim3(16, 16, B), thr>>>(x, (size_t)3 * N, N, x, (size_t)3 * N, 3, N, dist, xxp, nullptr);
    k_topk<<<B * N / 8, thr>>>(dist, idxp);
    k_g128<1><<<dim3(16, 1, B), thr>>>(wcat, 0, 128, x, (size_t)3 * N, 3, 128, pq, nullptr, nullptr);
    k_gmax<64><<<dim3(N / 4, B), thr>>>(pq, idxp, gs[0], bs[0], xc, 0);

    // ---- stage 2: F=xc[0:64], C=64, O=64, choff=64 ----
    const float* F2 = xc;
    k_wprep<<<16, thr>>>(W2, 64, 64, wcat);
    k_xx<<<dim3(N / 256, B), thr>>>(F2, bs512, 64, xxp);
    k_g128<0><<<dim3(16, 16, B), thr>>>(F2, bs512, N, F2, bs512, 64, N, dist, xxp, nullptr);
    k_topk<<<B * N / 8, thr>>>(dist, idxp);
    k_g128<1><<<dim3(16, 1, B), thr>>>(wcat, 0, 128, F2, bs512, 64, 128, pq, nullptr, nullptr);
    k_gmax<64><<<dim3(N / 4, B), thr>>>(pq, idxp, gs[1], bs[1], xc, 64);

    // ---- stage 3: F=xc[64:128], C=64, O=128, choff=128 ----
    const float* F3 = xc + (size_t)64 * N;
    k_wprep<<<32, thr>>>(W3, 128, 64, wcat);
    k_xx<<<dim3(N / 256, B), thr>>>(F3, bs512, 64, xxp);
    k_g128<0><<<dim3(16, 16, B), thr>>>(F3, bs512, N, F3, bs512, 64, N, dist, xxp, nullptr);
    k_topk<<<B * N / 8, thr>>>(dist, idxp);
    k_g128<1><<<dim3(16, 2, B), thr>>>(wcat, 0, 256, F3, bs512, 64, 256, pq, nullptr, nullptr);
    k_gmax<128><<<dim3(N / 2, B), thr>>>(pq, idxp, gs[2], bs[2], xc, 128);

    // ---- stage 4: F=xc[128:256], C=128, O=256, choff=256 ----
    const float* F4 = xc + (size_t)128 * N;
    k_wprep<<<128, thr>>>(W4, 256, 128, wcat);
    k_xx<<<dim3(N / 256, B), thr>>>(F4, bs512, 128, xxp);
    k_g128<0><<<dim3(16, 16, B), thr>>>(F4, bs512, N, F4, bs512, 128, N, dist, xxp, nullptr);
    k_topk<<<B * N / 8, thr>>>(dist, idxp);
    k_g128<1><<<dim3(16, 4, B), thr>>>(wcat, 0, 512, F4, bs512, 128, 512, pq, nullptr, nullptr);
    k_gmax<256><<<dim3(N, B), thr>>>(pq, idxp, gs[3], bs[3], xc, 256);

    // ---- conv5 + pooling + head ----
    k_trs<<<2048, thr>>>(W5, 512, 1024, 512, w5t);
    k_g128<2><<<dim3(16, 8, B), thr>>>(w5t, 0, 1024, xc, bs512, 512, 1024, yp, gs[4], bs[4]);
    k_pool<<<dim3(1024, B), thr>>>(yp, poolp);
    k_fc<1><<<(16 * 512 * 32) / 256, thr>>>(poolp, 2048, L1w, nullptr, gs[5], bs[5], 512, h1);
    k_fc<1><<<(16 * 256 * 32) / 256, thr>>>(h1, 512, L2w, L2b, gs[6], bs[6], 256, h2);
    k_fc<0><<<(16 * 40 * 32 + 255) / 256, thr>>>(h2, 256, L3w, L3b, nullptr, nullptr, 40, out);
}

// round 12
// speedup vs baseline: 1.9339x; 1.3373x over previous
#include <cuda_runtime.h>
#include <cstdint>

#define BNS 0.9999950000375f  // 1/sqrt(1+1e-5)
constexpr int B = 16;
constexpr int N = 2048;

// ----------------- device scratch (no allocations) -----------------
__device__ float g_dist[(size_t)B * N * N];        // 268 MB
__device__ float g_xx[B * N];
__device__ int   g_idx[B * N * 20];
__device__ float g_xc[(size_t)B * 512 * N];        // channel-major concat feats
__device__ float g_pq[(size_t)B * N * 512];        // point-major P|Q per stage
__device__ float g_y[(size_t)B * 1024 * N];
__device__ float g_wcat[128 * 512];                // Wt_cat: C x 2O
__device__ float g_w5t[512 * 1024];
__device__ float g_pool[B * 2048];
__device__ float g_h1[B * 512];
__device__ float g_h2[B * 256];

// ----------------- helpers -----------------
// build Wt_cat (C x 2O): cols [0,O) = Wd = W[:,0:C]; cols [O,2O) = Wc - Wd
__global__ void k_wprep(const float* __restrict__ W, int O, int C, float* __restrict__ Wt) {
    int t = blockIdx.x * 256 + threadIdx.x;
    if (t >= O * C) return;
    int o = t / C, c = t - o * C;
    float wd = W[(size_t)o * 2 * C + c];
    float wc = W[(size_t)o * 2 * C + C + c];
    Wt[(size_t)c * 2 * O + o] = wd;
    Wt[(size_t)c * 2 * O + O + o] = wc - wd;
}

// W (O x rstride) cols [0,C) -> Wt (C x O)
__global__ void k_trs(const float* __restrict__ W, int rstride, int O, int C,
                      float* __restrict__ Wt) {
    int t = blockIdx.x * 256 + threadIdx.x;
    if (t >= O * C) return;
    int o = t / C, c = t - o * C;
    Wt[(size_t)c * O + o] = W[(size_t)o * rstride + c];
}

__global__ void k_xx(const float* __restrict__ F, size_t bstride, int C,
                     float* __restrict__ xx) {
    int b = blockIdx.y, i = blockIdx.x * 256 + threadIdx.x;
    const float* Fb = F + (size_t)b * bstride;
    float s = 0.f;
    for (int c = 0; c < C; c++) { float v = Fb[(size_t)c * N + i]; s = fmaf(v, v, s); }
    xx[b * N + i] = s;
}

// ----------------- 128x128 tiled GEMM, 8x8 per thread -----------------
// acc[i][j] = sum_c A[c][o0+ty*8+i] * Bm[c][n0+tx*8+j]
// EPI 0: dist   out[(b*N+row)*N+col] = 2*acc - xx[row] - xx[col]      (e1 = xx)
// EPI 1: PM     out[(b*N+col)*M+row] = acc                            (point-major)
// EPI 2: BN     out[(b*M+row)*N+col] = lrelu(acc*g*BNS + bb)          (e1=g, e2=bb)
template <int EPI>
__global__ __launch_bounds__(256, 2) void k_g128(
    const float* __restrict__ A, size_t a_bs, int lda,
    const float* __restrict__ Bm, size_t b_bs,
    int C, int M, float* __restrict__ out,
    const float* __restrict__ e1, const float* __restrict__ e2) {
    __shared__ float sA[8][128];
    __shared__ float sB[8][128];
    int b = blockIdx.z, o0 = blockIdx.y * 128, n0 = blockIdx.x * 128;
    const float* Ab = A + (size_t)b * a_bs;
    const float* Bb = Bm + (size_t)b * b_bs;
    int tid = threadIdx.x, tx = tid & 15, ty = tid >> 4;
    int lr = tid >> 5, lc = (tid & 31) * 4;
    float acc[8][8] = {};
    for (int c0 = 0; c0 < C; c0 += 8) {
        int c = c0 + lr;
        float4 va = make_float4(0.f, 0.f, 0.f, 0.f), vb = va;
        if (c < C) {
            va = *(const float4*)&Ab[(size_t)c * lda + o0 + lc];
            vb = *(const float4*)&Bb[(size_t)c * N + n0 + lc];
        }
        *(float4*)&sA[lr][lc] = va;
        *(float4*)&sB[lr][lc] = vb;
        __syncthreads();
#pragma unroll
        for (int kk = 0; kk < 8; kk++) {
            float a[8], bv[8];
            *(float4*)&a[0]  = *(const float4*)&sA[kk][ty * 8];
            *(float4*)&a[4]  = *(const float4*)&sA[kk][ty * 8 + 4];
            *(float4*)&bv[0] = *(const float4*)&sB[kk][tx * 8];
            *(float4*)&bv[4] = *(const float4*)&sB[kk][tx * 8 + 4];
#pragma unroll
            for (int i = 0; i < 8; i++)
#pragma unroll
                for (int j = 0; j < 8; j++) acc[i][j] = fmaf(a[i], bv[j], acc[i][j]);
        }
        __syncthreads();
    }
    if (EPI == 0) {
        const float* xb = e1 + b * N;
#pragma unroll
        for (int i = 0; i < 8; i++) {
            int row = o0 + ty * 8 + i;
            float xi = xb[row];
            float* orow = out + ((size_t)b * N + row) * N + n0 + tx * 8;
#pragma unroll
            for (int j = 0; j < 8; j++)
                orow[j] = 2.f * acc[i][j] - xi - xb[n0 + tx * 8 + j];
        }
    } else if (EPI == 1) {
#pragma unroll
        for (int j = 0; j < 8; j++) {
            int col = n0 + tx * 8 + j;
            float* oc = out + ((size_t)b * N + col) * M + o0 + ty * 8;
            float4 v0 = make_float4(acc[0][j], acc[1][j], acc[2][j], acc[3][j]);
            float4 v1 = make_float4(acc[4][j], acc[5][j], acc[6][j], acc[7][j]);
            *(float4*)&oc[0] = v0;
            *(float4*)&oc[4] = v1;
        }
    } else {
#pragma unroll
        for (int i = 0; i < 8; i++) {
            int row = o0 + ty * 8 + i;
            float s = e1[row] * BNS, bi = e2[row];
            float* orow = out + ((size_t)b * M + row) * N + n0 + tx * 8;
#pragma unroll
            for (int j = 0; j < 8; j++) {
                float v = acc[i][j] * s + bi;
                orow[j] = v < 0.f ? 0.2f * v : v;
            }
        }
    }
}

// ----------------- warp-distributed sorted top-20 -----------------
// lanes 0..19 hold the current top-20 (val,idx) sorted descending; thresh = lane19's val.
__global__ __launch_bounds__(256) void k_topk(const float* __restrict__ dist,
                                              int* __restrict__ idxo) {
    int row = blockIdx.x * 8 + (threadIdx.x >> 5);
    int lane = threadIdx.x & 31;
    const float* dr = dist + (size_t)row * N;
    float val = -3e38f; int idx = 0;
    float thresh = -3e38f;
    for (int s = 0; s < N / 32; s++) {
        float d = dr[s * 32 + lane];
        unsigned ball = __ballot_sync(0xffffffffu, d > thresh);
        while (ball) {
            int src = __ffs(ball) - 1;
            ball &= ball - 1;
            float xv = __shfl_sync(0xffffffffu, d, src);
            if (xv <= thresh) continue;  // thresh may have risen (uniform check)
            int xj = s * 32 + src;
            unsigned bigger = __ballot_sync(0xffffffffu, val > xv);
            int pos = __popc(bigger & 0xFFFFFu);  // rank among lanes 0..19
            float upv = __shfl_up_sync(0xffffffffu, val, 1);
            int   upi = __shfl_up_sync(0xffffffffu, idx, 1);
            if (lane == pos)      { val = xv;  idx = xj; }
            else if (lane > pos)  { val = upv; idx = upi; }
            thresh = __shfl_sync(0xffffffffu, val, 19);
        }
    }
    if (lane < 20) idxo[(size_t)row * 20 + lane] = idx;
}

// ----------------- gather-max + BN + lrelu -----------------
// PQ point-major (B,N,2O). out[o][n] = lrelu(bn(max_k PQ[idx[n][k]][o] + PQ[n][O+o]))
template <int O>
__global__ void k_gmax(const float* __restrict__ PQ, const int* __restrict__ idx,
                       const float* __restrict__ g, const float* __restrict__ bb,
                       float* __restrict__ xc, int choff) {
    constexpr int PTS = 256 / O;
    int b = blockIdx.y;
    int n = blockIdx.x * PTS + (threadIdx.x >> (O == 64 ? 6 : (O == 128 ? 7 : 8)));
    int o = threadIdx.x & (O - 1);
    const float* Pb = PQ + (size_t)b * N * (2 * O);
    const int* ir = idx + ((size_t)b * N + n) * 20;
    float m = -3e38f;
#pragma unroll
    for (int k = 0; k < 20; k++) {
        int j = __ldg(&ir[k]);
        m = fmaxf(m, __ldg(&Pb[(size_t)j * (2 * O) + o]));
    }
    float v = m + Pb[(size_t)n * (2 * O) + O + o];
    v = v * (g[o] * BNS) + bb[o];
    v = v < 0.f ? 0.2f * v : v;
    xc[((size_t)b * 512 + choff + o) * N + n] = v;
}

// ----------------- pooling + FC head -----------------
__global__ void k_pool(const float* __restrict__ y, float* __restrict__ p) {
    __shared__ float smx[256], ssm[256];
    int b = blockIdx.y, o = blockIdx.x, tid = threadIdx.x;
    const float* row = y + ((size_t)b * 1024 + o) * N;
    float mx = -3e38f, sm = 0.f;
    for (int n = tid; n < N; n += 256) { float v = row[n]; mx = fmaxf(mx, v); sm += v; }
    smx[tid] = mx; ssm[tid] = sm; __syncthreads();
    for (int s = 128; s; s >>= 1) {
        if (tid < s) { smx[tid] = fmaxf(smx[tid], smx[tid + s]); ssm[tid] += ssm[tid + s]; }
        __syncthreads();
    }
    if (tid == 0) { p[b * 2048 + o] = smx[0]; p[b * 2048 + 1024 + o] = ssm[0] * (1.f / 2048.f); }
}

template <int MODE>  // 0: +bias, 1: (+bias)+BN+lrelu
__global__ void k_fc(const float* __restrict__ in, int Cin, const float* __restrict__ W,
                     const float* __restrict__ bias, const float* __restrict__ g,
                     const float* __restrict__ bb, int O, float* __restrict__ outp) {
    int gw = (blockIdx.x * blockDim.x + threadIdx.x) >> 5;
    int lane = threadIdx.x & 31;
    if (gw >= 16 * O) return;
    int b = gw / O, o = gw - b * O;
    const float* ib = in + (size_t)b * Cin;
    const float* wr = W + (size_t)o * Cin;
    float s = 0.f;
    for (int c = lane; c < Cin; c += 32) s = fmaf(ib[c], wr[c], s);
#pragma unroll
    for (int off = 16; off; off >>= 1) s += __shfl_xor_sync(0xffffffffu, s, off);
    if (lane == 0) {
        float v = s + (bias ? bias[o] : 0.f);
        if (MODE == 1) { v = v * (g[o] * BNS) + bb[o]; v = v < 0.f ? 0.2f * v : v; }
        outp[b * O + o] = v;
    }
}

extern "C" void kernel_launch(void* const* d_in, const int* in_sizes, int n_in,
                              void* d_out, int out_size) {
    (void)in_sizes; (void)n_in; (void)out_size;
    const float* x  = (const float*)d_in[0];
    const float* W1 = (const float*)d_in[1];
    const float* W2 = (const float*)d_in[2];
    const float* W3 = (const float*)d_in[3];
    const float* W4 = (const float*)d_in[4];
    const float* W5 = (const float*)d_in[5];
    const float *gs[7], *bs[7];
    for (int i = 0; i < 7; i++) { gs[i] = (const float*)d_in[6 + 2 * i]; bs[i] = (const float*)d_in[7 + 2 * i]; }
    const float* L1w = (const float*)d_in[20];
    const float* L2w = (const float*)d_in[21];
    const float* L2b = (const float*)d_in[22];
    const float* L3w = (const float*)d_in[23];
    const float* L3b = (const float*)d_in[24];
    float* out = (float*)d_out;

    float *dist, *xxp, *xc, *pq, *yp, *wcat, *w5t, *poolp, *h1, *h2;
    int* idxp;
    cudaGetSymbolAddress((void**)&dist, g_dist);
    cudaGetSymbolAddress((void**)&xxp, g_xx);
    cudaGetSymbolAddress((void**)&idxp, g_idx);
    cudaGetSymbolAddress((void**)&xc, g_xc);
    cudaGetSymbolAddress((void**)&pq, g_pq);
    cudaGetSymbolAddress((void**)&yp, g_y);
    cudaGetSymbolAddress((void**)&wcat, g_wcat);
    cudaGetSymbolAddress((void**)&w5t, g_w5t);
    cudaGetSymbolAddress((void**)&poolp, g_pool);
    cudaGetSymbolAddress((void**)&h1, g_h1);
    cudaGetSymbolAddress((void**)&h2, g_h2);

    dim3 thr(256);
    size_t bs512 = (size_t)512 * N;

    // ---- stage 1: F=x, C=3, O=64, choff=0 ----
    k_wprep<<<1, thr>>>(W1, 64, 3, wcat);
    k_xx<<<dim3(N / 256, B), thr>>>(x, (size_t)3 * N, 3, xxp);
    k_g128<0><<<dim3(16, 16, B), thr>>>(x, (size_t)3 * N, N, x, (size_t)3 * N, 3, N, dist, xxp, nullptr);
    k_topk<<<B * N / 8, thr>>>(dist, idxp);
    k_g128<1><<<dim3(16, 1, B), thr>>>(wcat, 0, 128, x, (size_t)3 * N, 3, 128, pq, nullptr, nullptr);
    k_gmax<64><<<dim3(N / 4, B), thr>>>(pq, idxp, gs[0], bs[0], xc, 0);

    // ---- stage 2: F=xc[0:64], C=64, O=64, choff=64 ----
    const float* F2 = xc;
    k_wprep<<<16, thr>>>(W2, 64, 64, wcat);
    k_xx<<<dim3(N / 256, B), thr>>>(F2, bs512, 64, xxp);
    k_g128<0><<<dim3(16, 16, B), thr>>>(F2, bs512, N, F2, bs512, 64, N, dist, xxp, nullptr);
    k_topk<<<B * N / 8, thr>>>(dist, idxp);
    k_g128<1><<<dim3(16, 1, B), thr>>>(wcat, 0, 128, F2, bs512, 64, 128, pq, nullptr, nullptr);
    k_gmax<64><<<dim3(N / 4, B), thr>>>(pq, idxp, gs[1], bs[1], xc, 64);

    // ---- stage 3: F=xc[64:128], C=64, O=128, choff=128 ----
    const float* F3 = xc + (size_t)64 * N;
    k_wprep<<<32, thr>>>(W3, 128, 64, wcat);
    k_xx<<<dim3(N / 256, B), thr>>>(F3, bs512, 64, xxp);
    k_g128<0><<<dim3(16, 16, B), thr>>>(F3, bs512, N, F3, bs512, 64, N, dist, xxp, nullptr);
    k_topk<<<B * N / 8, thr>>>(dist, idxp);
    k_g128<1><<<dim3(16, 2, B), thr>>>(wcat, 0, 256, F3, bs512, 64, 256, pq, nullptr, nullptr);
    k_gmax<128><<<dim3(N / 2, B), thr>>>(pq, idxp, gs[2], bs[2], xc, 128);

    // ---- stage 4: F=xc[128:256], C=128, O=256, choff=256 ----
    const float* F4 = xc + (size_t)128 * N;
    k_wprep<<<128, thr>>>(W4, 256, 128, wcat);
    k_xx<<<dim3(N / 256, B), thr>>>(F4, bs512, 128, xxp);
    k_g128<0><<<dim3(16, 16, B), thr>>>(F4, bs512, N, F4, bs512, 128, N, dist, xxp, nullptr);
    k_topk<<<B * N / 8, thr>>>(dist, idxp);
    k_g128<1><<<dim3(16, 4, B), thr>>>(wcat, 0, 512, F4, bs512, 128, 512, pq, nullptr, nullptr);
    k_gmax<256><<<dim3(N, B), thr>>>(pq, idxp, gs[3], bs[3], xc, 256);

    // ---- conv5 + pooling + head ----
    k_trs<<<2048, thr>>>(W5, 512, 1024, 512, w5t);
    k_g128<2><<<dim3(16, 8, B), thr>>>(w5t, 0, 1024, xc, bs512, 512, 1024, yp, gs[4], bs[4]);
    k_pool<<<dim3(1024, B), thr>>>(yp, poolp);
    k_fc<1><<<(16 * 512 * 32) / 256, thr>>>(poolp, 2048, L1w, nullptr, gs[5], bs[5], 512, h1);
    k_fc<1><<<(16 * 256 * 32) / 256, thr>>>(h1, 512, L2w, L2b, gs[6], bs[6], 256, h2);
    k_fc<0><<<(16 * 40 * 32 + 255) / 256, thr>>>(h2, 256, L3w, L3b, nullptr, nullptr, 40, out);
}

// round 13
// speedup vs baseline: 1.9677x; 1.0175x over previous
#include <cuda_runtime.h>
#include <cstdint>

#define BNS 0.9999950000375f  // 1/sqrt(1+1e-5)
constexpr int B = 16;
constexpr int N = 2048;

// ----------------- device scratch (no allocations) -----------------
__device__ float g_xx[B * N];
__device__ int   g_idx[B * N * 20];
__device__ float g_xc[(size_t)B * 512 * N];        // channel-major concat feats
__device__ float g_pq[(size_t)B * N * 512];        // point-major P|Q per stage
__device__ float g_y[(size_t)B * 1024 * N];
__device__ float g_wcat[128 * 512];                // Wt_cat: C x 2O
__device__ float g_w5t[512 * 1024];
__device__ float g_pool[B * 2048];
__device__ float g_h1[B * 512];
__device__ float g_h2[B * 256];

// ----------------- helpers -----------------
// build Wt_cat (C x 2O): cols [0,O) = Wd = W[:,0:C]; cols [O,2O) = Wc - Wd
__global__ void k_wprep(const float* __restrict__ W, int O, int C, float* __restrict__ Wt) {
    int t = blockIdx.x * 256 + threadIdx.x;
    if (t >= O * C) return;
    int o = t / C, c = t - o * C;
    float wd = W[(size_t)o * 2 * C + c];
    float wc = W[(size_t)o * 2 * C + C + c];
    Wt[(size_t)c * 2 * O + o] = wd;
    Wt[(size_t)c * 2 * O + O + o] = wc - wd;
}

// W (O x rstride) cols [0,C) -> Wt (C x O)
__global__ void k_trs(const float* __restrict__ W, int rstride, int O, int C,
                      float* __restrict__ Wt) {
    int t = blockIdx.x * 256 + threadIdx.x;
    if (t >= O * C) return;
    int o = t / C, c = t - o * C;
    Wt[(size_t)c * O + o] = W[(size_t)o * rstride + c];
}

__global__ void k_xx(const float* __restrict__ F, size_t bstride, int C,
                     float* __restrict__ xx) {
    int b = blockIdx.y, i = blockIdx.x * 256 + threadIdx.x;
    const float* Fb = F + (size_t)b * bstride;
    float s = 0.f;
    for (int c = 0; c < C; c++) { float v = Fb[(size_t)c * N + i]; s = fmaf(v, v, s); }
    xx[b * N + i] = s;
}

// ----------------- fused kNN: dist tile GEMM + warp top-20, no dist matrix -----------------
// Block: 32 query rows (i) x one batch. Loop j in 64-wide tiles.
// Selection key: 2*inner(i,j) - xx[j]   (dropping row-constant -xx[i] preserves order)
template <int C>
__global__ __launch_bounds__(256, 2) void k_knn(const float* __restrict__ F, size_t bstride,
                                                const float* __restrict__ xx,
                                                int* __restrict__ idxo) {
    extern __shared__ float sm[];
    float* As  = sm;                 // [C][32]
    float* Bs  = As + C * 32;        // [C][64]
    float* sD  = Bs + C * 64;        // [32][68]
    float* sXj = sD + 32 * 68;       // [64]
    int b = blockIdx.y, i0 = blockIdx.x * 32;
    const float* Fb = F + (size_t)b * bstride;
    int tid = threadIdx.x, lane = tid & 31, w = tid >> 5;
    int tx = tid & 15, ty = tid >> 4;

    for (int t = tid; t < C * 32; t += 256)
        As[t] = Fb[(size_t)(t >> 5) * N + i0 + (t & 31)];

    float val[4]; int idx[4]; float th[4];
#pragma unroll
    for (int r = 0; r < 4; r++) { val[r] = -3e38f; idx[r] = 0; th[r] = -3e38f; }
    __syncthreads();

    for (int j0 = 0; j0 < N; j0 += 64) {
        for (int t = tid; t < C * 64; t += 256)
            Bs[t] = Fb[(size_t)(t >> 6) * N + j0 + (t & 63)];
        if (tid < 64) sXj[tid] = xx[b * N + j0 + tid];
        __syncthreads();

        float acc[2][4] = {};
#pragma unroll 4
        for (int k = 0; k < C; k++) {
            float a0 = As[k * 32 + ty * 2];
            float a1 = As[k * 32 + ty * 2 + 1];
            float4 b4 = *(const float4*)&Bs[k * 64 + tx * 4];
            acc[0][0] = fmaf(a0, b4.x, acc[0][0]); acc[0][1] = fmaf(a0, b4.y, acc[0][1]);
            acc[0][2] = fmaf(a0, b4.z, acc[0][2]); acc[0][3] = fmaf(a0, b4.w, acc[0][3]);
            acc[1][0] = fmaf(a1, b4.x, acc[1][0]); acc[1][1] = fmaf(a1, b4.y, acc[1][1]);
            acc[1][2] = fmaf(a1, b4.z, acc[1][2]); acc[1][3] = fmaf(a1, b4.w, acc[1][3]);
        }
#pragma unroll
        for (int ii = 0; ii < 2; ii++)
#pragma unroll
            for (int jj = 0; jj < 4; jj++)
                sD[(ty * 2 + ii) * 68 + tx * 4 + jj] =
                    2.f * acc[ii][jj] - sXj[tx * 4 + jj];
        __syncthreads();

        // warp w owns rows 4w..4w+3; sorted top-20 in lanes 0..19
#pragma unroll
        for (int r = 0; r < 4; r++) {
            int row = (w << 2) + r;
#pragma unroll
            for (int h = 0; h < 2; h++) {
                float d = sD[row * 68 + h * 32 + lane];
                unsigned ball = __ballot_sync(0xffffffffu, d > th[r]);
                while (ball) {
                    int src = __ffs(ball) - 1;
                    ball &= ball - 1;
                    float xv = __shfl_sync(0xffffffffu, d, src);
                    if (xv <= th[r]) continue;
                    int xj = j0 + h * 32 + src;
                    unsigned bigger = __ballot_sync(0xffffffffu, val[r] > xv);
                    int pos = __popc(bigger & 0xFFFFFu);
                    float upv = __shfl_up_sync(0xffffffffu, val[r], 1);
                    int   upi = __shfl_up_sync(0xffffffffu, idx[r], 1);
                    if (lane == pos)     { val[r] = xv;  idx[r] = xj; }
                    else if (lane > pos) { val[r] = upv; idx[r] = upi; }
                    th[r] = __shfl_sync(0xffffffffu, val[r], 19);
                }
            }
        }
        __syncthreads();
    }
    if (lane < 20) {
#pragma unroll
        for (int r = 0; r < 4; r++)
            idxo[((size_t)b * N + i0 + (w << 2) + r) * 20 + lane] = idx[r];
    }
}

// ----------------- 128x128 tiled GEMM, 8x8 per thread -----------------
// EPI 1: PM  out[(b*N+col)*M+row] = acc                       (point-major)
// EPI 2: BN  out[(b*M+row)*N+col] = lrelu(acc*g*BNS + bb)     (e1=g, e2=bb)
template <int EPI>
__global__ __launch_bounds__(256, 2) void k_g128(
    const float* __restrict__ A, size_t a_bs, int lda,
    const float* __restrict__ Bm, size_t b_bs,
    int C, int M, float* __restrict__ out,
    const float* __restrict__ e1, const float* __restrict__ e2) {
    __shared__ float sA[8][128];
    __shared__ float sB[8][128];
    int b = blockIdx.z, o0 = blockIdx.y * 128, n0 = blockIdx.x * 128;
    const float* Ab = A + (size_t)b * a_bs;
    const float* Bb = Bm + (size_t)b * b_bs;
    int tid = threadIdx.x, tx = tid & 15, ty = tid >> 4;
    int lr = tid >> 5, lc = (tid & 31) * 4;
    float acc[8][8] = {};
    for (int c0 = 0; c0 < C; c0 += 8) {
        int c = c0 + lr;
        float4 va = make_float4(0.f, 0.f, 0.f, 0.f), vb = va;
        if (c < C) {
            va = *(const float4*)&Ab[(size_t)c * lda + o0 + lc];
            vb = *(const float4*)&Bb[(size_t)c * N + n0 + lc];
        }
        *(float4*)&sA[lr][lc] = va;
        *(float4*)&sB[lr][lc] = vb;
        __syncthreads();
#pragma unroll
        for (int kk = 0; kk < 8; kk++) {
            float a[8], bv[8];
            *(float4*)&a[0]  = *(const float4*)&sA[kk][ty * 8];
            *(float4*)&a[4]  = *(const float4*)&sA[kk][ty * 8 + 4];
            *(float4*)&bv[0] = *(const float4*)&sB[kk][tx * 8];
            *(float4*)&bv[4] = *(const float4*)&sB[kk][tx * 8 + 4];
#pragma unroll
            for (int i = 0; i < 8; i++)
#pragma unroll
                for (int j = 0; j < 8; j++) acc[i][j] = fmaf(a[i], bv[j], acc[i][j]);
        }
        __syncthreads();
    }
    if (EPI == 1) {
#pragma unroll
        for (int j = 0; j < 8; j++) {
            int col = n0 + tx * 8 + j;
            float* oc = out + ((size_t)b * N + col) * M + o0 + ty * 8;
            float4 v0 = make_float4(acc[0][j], acc[1][j], acc[2][j], acc[3][j]);
            float4 v1 = make_float4(acc[4][j], acc[5][j], acc[6][j], acc[7][j]);
            *(float4*)&oc[0] = v0;
            *(float4*)&oc[4] = v1;
        }
    } else {
#pragma unroll
        for (int i = 0; i < 8; i++) {
            int row = o0 + ty * 8 + i;
            float s = e1[row] * BNS, bi = e2[row];
            float* orow = out + ((size_t)b * M + row) * N + n0 + tx * 8;
#pragma unroll
            for (int j = 0; j < 8; j++) {
                float v = acc[i][j] * s + bi;
                orow[j] = v < 0.f ? 0.2f * v : v;
            }
        }
    }
}

// ----------------- gather-max + BN + lrelu -----------------
template <int O>
__global__ void k_gmax(const float* __restrict__ PQ, const int* __restrict__ idx,
                       const float* __restrict__ g, const float* __restrict__ bb,
                       float* __restrict__ xc, int choff) {
    constexpr int PTS = 256 / O;
    int b = blockIdx.y;
    int n = blockIdx.x * PTS + (threadIdx.x >> (O == 64 ? 6 : (O == 128 ? 7 : 8)));
    int o = threadIdx.x & (O - 1);
    const float* Pb = PQ + (size_t)b * N * (2 * O);
    const int* ir = idx + ((size_t)b * N + n) * 20;
    float m = -3e38f;
#pragma unroll
    for (int k = 0; k < 20; k++) {
        int j = __ldg(&ir[k]);
        m = fmaxf(m, __ldg(&Pb[(size_t)j * (2 * O) + o]));
    }
    float v = m + Pb[(size_t)n * (2 * O) + O + o];
    v = v * (g[o] * BNS) + bb[o];
    v = v < 0.f ? 0.2f * v : v;
    xc[((size_t)b * 512 + choff + o) * N + n] = v;
}

// ----------------- pooling + FC head -----------------
__global__ void k_pool(const float* __restrict__ y, float* __restrict__ p) {
    __shared__ float smx[256], ssm[256];
    int b = blockIdx.y, o = blockIdx.x, tid = threadIdx.x;
    const float* row = y + ((size_t)b * 1024 + o) * N;
    float mx = -3e38f, sm = 0.f;
    for (int n = tid; n < N; n += 256) { float v = row[n]; mx = fmaxf(mx, v); sm += v; }
    smx[tid] = mx; ssm[tid] = sm; __syncthreads();
    for (int s = 128; s; s >>= 1) {
        if (tid < s) { smx[tid] = fmaxf(smx[tid], smx[tid + s]); ssm[tid] += ssm[tid + s]; }
        __syncthreads();
    }
    if (tid == 0) { p[b * 2048 + o] = smx[0]; p[b * 2048 + 1024 + o] = ssm[0] * (1.f / 2048.f); }
}

template <int MODE>  // 0: +bias, 1: (+bias)+BN+lrelu
__global__ void k_fc(const float* __restrict__ in, int Cin, const float* __restrict__ W,
                     const float* __restrict__ bias, const float* __restrict__ g,
                     const float* __restrict__ bb, int O, float* __restrict__ outp) {
    int gw = (blockIdx.x * blockDim.x + threadIdx.x) >> 5;
    int lane = threadIdx.x & 31;
    if (gw >= 16 * O) return;
    int b = gw / O, o = gw - b * O;
    const float* ib = in + (size_t)b * Cin;
    const float* wr = W + (size_t)o * Cin;
    float s = 0.f;
    for (int c = lane; c < Cin; c += 32) s = fmaf(ib[c], wr[c], s);
#pragma unroll
    for (int off = 16; off; off >>= 1) s += __shfl_xor_sync(0xffffffffu, s, off);
    if (lane == 0) {
        float v = s + (bias ? bias[o] : 0.f);
        if (MODE == 1) { v = v * (g[o] * BNS) + bb[o]; v = v < 0.f ? 0.2f * v : v; }
        outp[b * O + o] = v;
    }
}

static int knn_smem(int C) { return (C * 32 + C * 64 + 32 * 68 + 64) * 4; }

extern "C" void kernel_launch(void* const* d_in, const int* in_sizes, int n_in,
                              void* d_out, int out_size) {
    (void)in_sizes; (void)n_in; (void)out_size;
    const float* x  = (const float*)d_in[0];
    const float* W1 = (const float*)d_in[1];
    const float* W2 = (const float*)d_in[2];
    const float* W3 = (const float*)d_in[3];
    const float* W4 = (const float*)d_in[4];
    const float* W5 = (const float*)d_in[5];
    const float *gs[7], *bs[7];
    for (int i = 0; i < 7; i++) { gs[i] = (const float*)d_in[6 + 2 * i]; bs[i] = (const float*)d_in[7 + 2 * i]; }
    const float* L1w = (const float*)d_in[20];
    const float* L2w = (const float*)d_in[21];
    const float* L2b = (const float*)d_in[22];
    const float* L3w = (const float*)d_in[23];
    const float* L3b = (const float*)d_in[24];
    float* out = (float*)d_out;

    float *xxp, *xc, *pq, *yp, *wcat, *w5t, *poolp, *h1, *h2;
    int* idxp;
    cudaGetSymbolAddress((void**)&xxp, g_xx);
    cudaGetSymbolAddress((void**)&idxp, g_idx);
    cudaGetSymbolAddress((void**)&xc, g_xc);
    cudaGetSymbolAddress((void**)&pq, g_pq);
    cudaGetSymbolAddress((void**)&yp, g_y);
    cudaGetSymbolAddress((void**)&wcat, g_wcat);
    cudaGetSymbolAddress((void**)&w5t, g_w5t);
    cudaGetSymbolAddress((void**)&poolp, g_pool);
    cudaGetSymbolAddress((void**)&h1, g_h1);
    cudaGetSymbolAddress((void**)&h2, g_h2);

    cudaFuncSetAttribute(k_knn<3>,   cudaFuncAttributeMaxDynamicSharedMemorySize, knn_smem(3));
    cudaFuncSetAttribute(k_knn<64>,  cudaFuncAttributeMaxDynamicSharedMemorySize, knn_smem(64));
    cudaFuncSetAttribute(k_knn<128>, cudaFuncAttributeMaxDynamicSharedMemorySize, knn_smem(128));

    dim3 thr(256);
    dim3 knng(N / 32, B);
    size_t bs512 = (size_t)512 * N;

    // ---- stage 1: F=x, C=3, O=64, choff=0 ----
    k_wprep<<<1, thr>>>(W1, 64, 3, wcat);
    k_xx<<<dim3(N / 256, B), thr>>>(x, (size_t)3 * N, 3, xxp);
    k_knn<3><<<knng, thr, knn_smem(3)>>>(x, (size_t)3 * N, xxp, idxp);
    k_g128<1><<<dim3(16, 1, B), thr>>>(wcat, 0, 128, x, (size_t)3 * N, 3, 128, pq, nullptr, nullptr);
    k_gmax<64><<<dim3(N / 4, B), thr>>>(pq, idxp, gs[0], bs[0], xc, 0);

    // ---- stage 2: F=xc[0:64], C=64, O=64, choff=64 ----
    const float* F2 = xc;
    k_wprep<<<16, thr>>>(W2, 64, 64, wcat);
    k_xx<<<dim3(N / 256, B), thr>>>(F2, bs512, 64, xxp);
    k_knn<64><<<knng, thr, knn_smem(64)>>>(F2, bs512, xxp, idxp);
    k_g128<1><<<dim3(16, 1, B), thr>>>(wcat, 0, 128, F2, bs512, 64, 128, pq, nullptr, nullptr);
    k_gmax<64><<<dim3(N / 4, B), thr>>>(pq, idxp, gs[1], bs[1], xc, 64);

    // ---- stage 3: F=xc[64:128], C=64, O=128, choff=128 ----
    const float* F3 = xc + (size_t)64 * N;
    k_wprep<<<32, thr>>>(W3, 128, 64, wcat);
    k_xx<<<dim3(N / 256, B), thr>>>(F3, bs512, 64, xxp);
    k_knn<64><<<knng, thr, knn_smem(64)>>>(F3, bs512, xxp, idxp);
    k_g128<1><<<dim3(16, 2, B), thr>>>(wcat, 0, 256, F3, bs512, 64, 256, pq, nullptr, nullptr);
    k_gmax<128><<<dim3(N / 2, B), thr>>>(pq, idxp, gs[2], bs[2], xc, 128);

    // ---- stage 4: F=xc[128:256], C=128, O=256, choff=256 ----
    const float* F4 = xc + (size_t)128 * N;
    k_wprep<<<128, thr>>>(W4, 256, 128, wcat);
    k_xx<<<dim3(N / 256, B), thr>>>(F4, bs512, 128, xxp);
    k_knn<128><<<knng, thr, knn_smem(128)>>>(F4, bs512, xxp, idxp);
    k_g128<1><<<dim3(16, 4, B), thr>>>(wcat, 0, 512, F4, bs512, 128, 512, pq, nullptr, nullptr);
    k_gmax<256><<<dim3(N, B), thr>>>(pq, idxp, gs[3], bs[3], xc, 256);

    // ---- conv5 + pooling + head ----
    k_trs<<<2048, thr>>>(W5, 512, 1024, 512, w5t);
    k_g128<2><<<dim3(16, 8, B), thr>>>(w5t, 0, 1024, xc, bs512, 512, 1024, yp, gs[4], bs[4]);
    k_pool<<<dim3(1024, B), thr>>>(yp, poolp);
    k_fc<1><<<(16 * 512 * 32) / 256, thr>>>(poolp, 2048, L1w, nullptr, gs[5], bs[5], 512, h1);
    k_fc<1><<<(16 * 256 * 32) / 256, thr>>>(h1, 512, L2w, L2b, gs[6], bs[6], 256, h2);
    k_fc<0><<<(16 * 40 * 32 + 255) / 256, thr>>>(h2, 256, L3w, L3b, nullptr, nullptr, 40, out);
}

// round 14
// speedup vs baseline: 2.1324x; 1.0837x over previous
#include <cuda_runtime.h>
#include <cstdint>

#define BNS 0.9999950000375f  // 1/sqrt(1+1e-5)
constexpr int B = 16;
constexpr int N = 2048;

// ----------------- device scratch (no allocations) -----------------
__device__ float  g_xx[B * N];
__device__ int    g_idx[B * N * 20];
__device__ float  g_xc[(size_t)B * 512 * N];        // channel-major concat feats
__device__ float  g_pq[(size_t)B * N * 512];        // point-major P|Q per stage
__device__ float2 g_part[(size_t)B * 1024 * 16];    // conv5 partial (max,sum) per col-tile
__device__ float  g_wcat[128 * 512];                // Wt_cat: C x 2O
__device__ float  g_w5t[512 * 1024];
__device__ float  g_pool[B * 2048];
__device__ float  g_h1[B * 512];
__device__ float  g_h2[B * 256];

// ----------------- helpers -----------------
// build Wt_cat (C x 2O): cols [0,O) = Wd = W[:,0:C]; cols [O,2O) = Wc - Wd
__global__ void k_wprep(const float* __restrict__ W, int O, int C, float* __restrict__ Wt) {
    int t = blockIdx.x * 256 + threadIdx.x;
    if (t >= O * C) return;
    int o = t / C, c = t - o * C;
    float wd = W[(size_t)o * 2 * C + c];
    float wc = W[(size_t)o * 2 * C + C + c];
    Wt[(size_t)c * 2 * O + o] = wd;
    Wt[(size_t)c * 2 * O + O + o] = wc - wd;
}

// W (O x rstride) cols [0,C) -> Wt (C x O)
__global__ void k_trs(const float* __restrict__ W, int rstride, int O, int C,
                      float* __restrict__ Wt) {
    int t = blockIdx.x * 256 + threadIdx.x;
    if (t >= O * C) return;
    int o = t / C, c = t - o * C;
    Wt[(size_t)c * O + o] = W[(size_t)o * rstride + c];
}

__global__ void k_xx(const float* __restrict__ F, size_t bstride, int C,
                     float* __restrict__ xx) {
    int b = blockIdx.y, i = blockIdx.x * 256 + threadIdx.x;
    const float* Fb = F + (size_t)b * bstride;
    float s = 0.f;
    for (int c = 0; c < C; c++) { float v = Fb[(size_t)c * N + i]; s = fmaf(v, v, s); }
    xx[b * N + i] = s;
}

// ----------------- fused kNN: 64x64 dist tile GEMM (4x4/thread) + warp top-20 -----------------
// Selection key: 2*inner(i,j) - xx[j]   (dropping row-constant -xx[i] preserves order)
template <int C>
__global__ __launch_bounds__(256, 2) void k_knn(const float* __restrict__ F, size_t bstride,
                                                const float* __restrict__ xx,
                                                int* __restrict__ idxo) {
    extern __shared__ float sm[];
    float* As  = sm;                 // [C][64]
    float* Bs  = As + C * 64;        // [C][64]
    float* sD  = Bs + C * 64;        // [64][68]
    float* sXj = sD + 64 * 68;       // [64]
    int b = blockIdx.y, i0 = blockIdx.x * 64;
    const float* Fb = F + (size_t)b * bstride;
    int tid = threadIdx.x, lane = tid & 31, w = tid >> 5;
    int tx = tid & 15, ty = tid >> 4;

    for (int t = tid; t < C * 64; t += 256)
        As[t] = Fb[(size_t)(t >> 6) * N + i0 + (t & 63)];

    float val[8]; int idx[8]; float th[8];
#pragma unroll
    for (int r = 0; r < 8; r++) { val[r] = -3e38f; idx[r] = 0; th[r] = -3e38f; }
    __syncthreads();

    for (int j0 = 0; j0 < N; j0 += 64) {
        for (int t = tid; t < C * 64; t += 256)
            Bs[t] = Fb[(size_t)(t >> 6) * N + j0 + (t & 63)];
        if (tid < 64) sXj[tid] = xx[b * N + j0 + tid];
        __syncthreads();

        float acc[4][4] = {};
#pragma unroll 4
        for (int k = 0; k < C; k++) {
            float4 a4 = *(const float4*)&As[k * 64 + ty * 4];
            float4 b4 = *(const float4*)&Bs[k * 64 + tx * 4];
            float a[4] = {a4.x, a4.y, a4.z, a4.w};
            float bv[4] = {b4.x, b4.y, b4.z, b4.w};
#pragma unroll
            for (int i = 0; i < 4; i++)
#pragma unroll
                for (int j = 0; j < 4; j++) acc[i][j] = fmaf(a[i], bv[j], acc[i][j]);
        }
#pragma unroll
        for (int ii = 0; ii < 4; ii++)
#pragma unroll
            for (int jj = 0; jj < 4; jj++)
                sD[(ty * 4 + ii) * 68 + tx * 4 + jj] =
                    2.f * acc[ii][jj] - sXj[tx * 4 + jj];
        __syncthreads();

        // warp w owns rows 8w..8w+7; sorted top-20 in lanes 0..19
#pragma unroll
        for (int r = 0; r < 8; r++) {
            int row = (w << 3) + r;
#pragma unroll
            for (int h = 0; h < 2; h++) {
                float d = sD[row * 68 + h * 32 + lane];
                unsigned ball = __ballot_sync(0xffffffffu, d > th[r]);
                while (ball) {
                    int src = __ffs(ball) - 1;
                    ball &= ball - 1;
                    float xv = __shfl_sync(0xffffffffu, d, src);
                    if (xv <= th[r]) continue;
                    int xj = j0 + h * 32 + src;
                    unsigned bigger = __ballot_sync(0xffffffffu, val[r] > xv);
                    int pos = __popc(bigger & 0xFFFFFu);
                    float upv = __shfl_up_sync(0xffffffffu, val[r], 1);
                    int   upi = __shfl_up_sync(0xffffffffu, idx[r], 1);
                    if (lane == pos)     { val[r] = xv;  idx[r] = xj; }
                    else if (lane > pos) { val[r] = upv; idx[r] = upi; }
                    th[r] = __shfl_sync(0xffffffffu, val[r], 19);
                }
            }
        }
        __syncthreads();
    }
    if (lane < 20) {
#pragma unroll
        for (int r = 0; r < 8; r++)
            idxo[((size_t)b * N + i0 + (w << 3) + r) * 20 + lane] = idx[r];
    }
}

// ----------------- 128x128 tiled GEMM, 8x8/thread, double-buffered smem -----------------
// EPI 1: PM  out[(b*N+col)*M+row] = acc                        (point-major)
// EPI 2: BN+lrelu + partial pool: part[(b*M+row)*16 + bx] = (max_col, sum_col)
template <int EPI>
__global__ __launch_bounds__(256, 2) void k_g128(
    const float* __restrict__ A, size_t a_bs, int lda,
    const float* __restrict__ Bm, size_t b_bs,
    int C, int M, float* __restrict__ out,
    const float* __restrict__ e1, const float* __restrict__ e2,
    float2* __restrict__ part) {
    __shared__ float sA[2][8][128];
    __shared__ float sB[2][8][128];
    __shared__ float redm[128 * 16];
    __shared__ float reds[128 * 16];
    int b = blockIdx.z, o0 = blockIdx.y * 128, n0 = blockIdx.x * 128;
    const float* Ab = A + (size_t)b * a_bs;
    const float* Bb = Bm + (size_t)b * b_bs;
    int tid = threadIdx.x, tx = tid & 15, ty = tid >> 4;
    int lr = tid >> 5, lc = (tid & 31) * 4;
    float acc[8][8] = {};
    int T = (C + 7) / 8;
    float4 ra = make_float4(0.f, 0.f, 0.f, 0.f), rb = ra;
    if (lr < C) {
        ra = *(const float4*)&Ab[(size_t)lr * lda + o0 + lc];
        rb = *(const float4*)&Bb[(size_t)lr * N + n0 + lc];
    }
    int p = 0;
    for (int t = 0; t < T; t++) {
        *(float4*)&sA[p][lr][lc] = ra;
        *(float4*)&sB[p][lr][lc] = rb;
        __syncthreads();
        if (t + 1 < T) {
            int c = (t + 1) * 8 + lr;
            ra = make_float4(0.f, 0.f, 0.f, 0.f); rb = ra;
            if (c < C) {
                ra = *(const float4*)&Ab[(size_t)c * lda + o0 + lc];
                rb = *(const float4*)&Bb[(size_t)c * N + n0 + lc];
            }
        }
#pragma unroll
        for (int kk = 0; kk < 8; kk++) {
            float a[8], bv[8];
            *(float4*)&a[0]  = *(const float4*)&sA[p][kk][ty * 8];
            *(float4*)&a[4]  = *(const float4*)&sA[p][kk][ty * 8 + 4];
            *(float4*)&bv[0] = *(const float4*)&sB[p][kk][tx * 8];
            *(float4*)&bv[4] = *(const float4*)&sB[p][kk][tx * 8 + 4];
#pragma unroll
            for (int i = 0; i < 8; i++)
#pragma unroll
                for (int j = 0; j < 8; j++) acc[i][j] = fmaf(a[i], bv[j], acc[i][j]);
        }
        p ^= 1;
    }
    if (EPI == 1) {
#pragma unroll
        for (int j = 0; j < 8; j++) {
            int col = n0 + tx * 8 + j;
            float* oc = out + ((size_t)b * N + col) * M + o0 + ty * 8;
            float4 v0 = make_float4(acc[0][j], acc[1][j], acc[2][j], acc[3][j]);
            float4 v1 = make_float4(acc[4][j], acc[5][j], acc[6][j], acc[7][j]);
            *(float4*)&oc[0] = v0;
            *(float4*)&oc[4] = v1;
        }
    } else {
#pragma unroll
        for (int i = 0; i < 8; i++) {
            int row = o0 + ty * 8 + i;
            float s = e1[row] * BNS, bi = e2[row];
            float mx = -3e38f, sm = 0.f;
#pragma unroll
            for (int j = 0; j < 8; j++) {
                float v = acc[i][j] * s + bi;
                v = v < 0.f ? 0.2f * v : v;
                mx = fmaxf(mx, v); sm += v;
            }
            redm[(ty * 8 + i) * 16 + tx] = mx;
            reds[(ty * 8 + i) * 16 + tx] = sm;
        }
        __syncthreads();
        if (tid < 128) {
            float mx = -3e38f, sm = 0.f;
#pragma unroll
            for (int t = 0; t < 16; t++) {
                mx = fmaxf(mx, redm[tid * 16 + t]);
                sm += reds[tid * 16 + t];
            }
            part[((size_t)b * M + o0 + tid) * 16 + blockIdx.x] = make_float2(mx, sm);
        }
    }
}

// ----------------- gather-max + BN + lrelu -----------------
template <int O>
__global__ void k_gmax(const float* __restrict__ PQ, const int* __restrict__ idx,
                       const float* __restrict__ g, const float* __restrict__ bb,
                       float* __restrict__ xc, int choff) {
    constexpr int PTS = 256 / O;
    int b = blockIdx.y;
    int n = blockIdx.x * PTS + (threadIdx.x >> (O == 64 ? 6 : (O == 128 ? 7 : 8)));
    int o = threadIdx.x & (O - 1);
    const float* Pb = PQ + (size_t)b * N * (2 * O);
    const int* ir = idx + ((size_t)b * N + n) * 20;
    float m = -3e38f;
#pragma unroll
    for (int k = 0; k < 20; k++) {
        int j = __ldg(&ir[k]);
        m = fmaxf(m, __ldg(&Pb[(size_t)j * (2 * O) + o]));
    }
    float v = m + Pb[(size_t)n * (2 * O) + O + o];
    v = v * (g[o] * BNS) + bb[o];
    v = v < 0.f ? 0.2f * v : v;
    xc[((size_t)b * 512 + choff + o) * N + n] = v;
}

// ----------------- final pooling reduce + FC head -----------------
__global__ void k_pool2(const float2* __restrict__ part, float* __restrict__ p) {
    int t = blockIdx.x * 256 + threadIdx.x;       // 0 .. B*1024-1
    int b = t >> 10, o = t & 1023;
    const float2* pr = part + (size_t)t * 16;
    float mx = -3e38f, s = 0.f;
#pragma unroll
    for (int i = 0; i < 16; i++) { float2 v = pr[i]; mx = fmaxf(mx, v.x); s += v.y; }
    p[b * 2048 + o] = mx;
    p[b * 2048 + 1024 + o] = s * (1.f / 2048.f);
}

template <int MODE>  // 0: +bias, 1: (+bias)+BN+lrelu
__global__ void k_fc(const float* __restrict__ in, int Cin, const float* __restrict__ W,
                     const float* __restrict__ bias, const float* __restrict__ g,
                     const float* __restrict__ bb, int O, float* __restrict__ outp) {
    int gw = (blockIdx.x * blockDim.x + threadIdx.x) >> 5;
    int lane = threadIdx.x & 31;
    if (gw >= 16 * O) return;
    int b = gw / O, o = gw - b * O;
    const float* ib = in + (size_t)b * Cin;
    const float* wr = W + (size_t)o * Cin;
    float s = 0.f;
    for (int c = lane; c < Cin; c += 32) s = fmaf(ib[c], wr[c], s);
#pragma unroll
    for (int off = 16; off; off >>= 1) s += __shfl_xor_sync(0xffffffffu, s, off);
    if (lane == 0) {
        float v = s + (bias ? bias[o] : 0.f);
        if (MODE == 1) { v = v * (g[o] * BNS) + bb[o]; v = v < 0.f ? 0.2f * v : v; }
        outp[b * O + o] = v;
    }
}

static int knn_smem(int C) { return (C * 64 * 2 + 64 * 68 + 64) * 4; }

extern "C" void kernel_launch(void* const* d_in, const int* in_sizes, int n_in,
                              void* d_out, int out_size) {
    (void)in_sizes; (void)n_in; (void)out_size;
    const float* x  = (const float*)d_in[0];
    const float* W1 = (const float*)d_in[1];
    const float* W2 = (const float*)d_in[2];
    const float* W3 = (const float*)d_in[3];
    const float* W4 = (const float*)d_in[4];
    const float* W5 = (const float*)d_in[5];
    const float *gs[7], *bs[7];
    for (int i = 0; i < 7; i++) { gs[i] = (const float*)d_in[6 + 2 * i]; bs[i] = (const float*)d_in[7 + 2 * i]; }
    const float* L1w = (const float*)d_in[20];
    const float* L2w = (const float*)d_in[21];
    const float* L2b = (const float*)d_in[22];
    const float* L3w = (const float*)d_in[23];
    const float* L3b = (const float*)d_in[24];
    float* out = (float*)d_out;

    float *xxp, *xc, *pq, *wcat, *w5t, *poolp, *h1, *h2;
    float2* partp;
    int* idxp;
    cudaGetSymbolAddress((void**)&xxp, g_xx);
    cudaGetSymbolAddress((void**)&idxp, g_idx);
    cudaGetSymbolAddress((void**)&xc, g_xc);
    cudaGetSymbolAddress((void**)&pq, g_pq);
    cudaGetSymbolAddress((void**)&partp, g_part);
    cudaGetSymbolAddress((void**)&wcat, g_wcat);
    cudaGetSymbolAddress((void**)&w5t, g_w5t);
    cudaGetSymbolAddress((void**)&poolp, g_pool);
    cudaGetSymbolAddress((void**)&h1, g_h1);
    cudaGetSymbolAddress((void**)&h2, g_h2);

    cudaFuncSetAttribute(k_knn<3>,   cudaFuncAttributeMaxDynamicSharedMemorySize, knn_smem(3));
    cudaFuncSetAttribute(k_knn<64>,  cudaFuncAttributeMaxDynamicSharedMemorySize, knn_smem(64));
    cudaFuncSetAttribute(k_knn<128>, cudaFuncAttributeMaxDynamicSharedMemorySize, knn_smem(128));

    dim3 thr(256);
    dim3 knng(N / 64, B);
    size_t bs512 = (size_t)512 * N;

    // ---- stage 1: F=x, C=3, O=64, choff=0 ----
    k_wprep<<<1, thr>>>(W1, 64, 3, wcat);
    k_xx<<<dim3(N / 256, B), thr>>>(x, (size_t)3 * N, 3, xxp);
    k_knn<3><<<knng, thr, knn_smem(3)>>>(x, (size_t)3 * N, xxp, idxp);
    k_g128<1><<<dim3(16, 1, B), thr>>>(wcat, 0, 128, x, (size_t)3 * N, 3, 128, pq, nullptr, nullptr, nullptr);
    k_gmax<64><<<dim3(N / 4, B), thr>>>(pq, idxp, gs[0], bs[0], xc, 0);

    // ---- stage 2: F=xc[0:64], C=64, O=64, choff=64 ----
    const float* F2 = xc;
    k_wprep<<<16, thr>>>(W2, 64, 64, wcat);
    k_xx<<<dim3(N / 256, B), thr>>>(F2, bs512, 64, xxp);
    k_knn<64><<<knng, thr, knn_smem(64)>>>(F2, bs512, xxp, idxp);
    k_g128<1><<<dim3(16, 1, B), thr>>>(wcat, 0, 128, F2, bs512, 64, 128, pq, nullptr, nullptr, nullptr);
    k_gmax<64><<<dim3(N / 4, B), thr>>>(pq, idxp, gs[1], bs[1], xc, 64);

    // ---- stage 3: F=xc[64:128], C=64, O=128, choff=128 ----
    const float* F3 = xc + (size_t)64 * N;
    k_wprep<<<32, thr>>>(W3, 128, 64, wcat);
    k_xx<<<dim3(N / 256, B), thr>>>(F3, bs512, 64, xxp);
    k_knn<64><<<knng, thr, knn_smem(64)>>>(F3, bs512, xxp, idxp);
    k_g128<1><<<dim3(16, 2, B), thr>>>(wcat, 0, 256, F3, bs512, 64, 256, pq, nullptr, nullptr, nullptr);
    k_gmax<128><<<dim3(N / 2, B), thr>>>(pq, idxp, gs[2], bs[2], xc, 128);

    // ---- stage 4: F=xc[128:256], C=128, O=256, choff=256 ----
    const float* F4 = xc + (size_t)128 * N;
    k_wprep<<<128, thr>>>(W4, 256, 128, wcat);
    k_xx<<<dim3(N / 256, B), thr>>>(F4, bs512, 128, xxp);
    k_knn<128><<<knng, thr, knn_smem(128)>>>(F4, bs512, xxp, idxp);
    k_g128<1><<<dim3(16, 4, B), thr>>>(wcat, 0, 512, F4, bs512, 128, 512, pq, nullptr, nullptr, nullptr);
    k_gmax<256><<<dim3(N, B), thr>>>(pq, idxp, gs[3], bs[3], xc, 256);

    // ---- conv5 (+fused partial pooling) + head ----
    k_trs<<<2048, thr>>>(W5, 512, 1024, 512, w5t);
    k_g128<2><<<dim3(16, 8, B), thr>>>(w5t, 0, 1024, xc, bs512, 512, 1024, nullptr, gs[4], bs[4], partp);
    k_pool2<<<(B * 1024) / 256, thr>>>(partp, poolp);
    k_fc<1><<<(16 * 512 * 32) / 256, thr>>>(poolp, 2048, L1w, nullptr, gs[5], bs[5], 512, h1);
    k_fc<1><<<(16 * 256 * 32) / 256, thr>>>(h1, 512, L2w, L2b, gs[6], bs[6], 256, h2);
    k_fc<0><<<(16 * 40 * 32 + 255) / 256, thr>>>(h2, 256, L3w, L3b, nullptr, nullptr, 40, out);
}